// round 9
// baseline (speedup 1.0000x reference)
#include <cuda_runtime.h>
#include <math.h>
#include <stdint.h>

#define Bmax 4
#define C_ 64
#define H_ 128
#define W_ 128
#define O_ 64
#define K_ 9
#define HW_ (H_*W_)

__device__ __forceinline__ uint32_t cvt_h2(float hi, float lo) {
    uint32_t r; asm("cvt.rn.f16x2.f32 %0, %1, %2;" : "=r"(r) : "f"(hi), "f"(lo)); return r;
}
__device__ __forceinline__ void mma16(float4 &d, uint32_t a0, uint32_t a1, uint32_t a2, uint32_t a3,
                                      uint32_t b0, uint32_t b1) {
    asm("mma.sync.aligned.m16n8k16.row.col.f32.f16.f16.f32 "
        "{%0,%1,%2,%3},{%4,%5,%6,%7},{%8,%9},{%0,%1,%2,%3};"
        : "+f"(d.x), "+f"(d.y), "+f"(d.z), "+f"(d.w)
        : "r"(a0), "r"(a1), "r"(a2), "r"(a3), "r"(b0), "r"(b1));
}

// ---------------- device scratch ----------------
__device__ float g_xn[Bmax*HW_*C_ + 16384];   // NHWC x (fp32), padded
// fp16 B fragments, per-thread order (uint2 = {b0,b1} half2 pairs):
__device__ uint2 g_wt3h[K_*4*8*32];           // main: [k][ks(4)][j(8)][t(32)]
__device__ uint2 g_w1h[K_*4*4*32];            // om:   [k][ks(4)][j(4)][t(32)]

// ---------------- NCHW -> NHWC transpose (2 h-rows per block) ----------------
__global__ __launch_bounds__(256)
void k_transpose(const float* __restrict__ x) {
    __shared__ float t[2][2][32][33];
    int b  = blockIdx.z;
    int h0 = blockIdx.y * 2;
    int w0 = blockIdx.x * 32;
    int tid = threadIdx.x;
    int r  = tid >> 3;
    int q  = tid & 7;
#pragma unroll
    for (int hh = 0; hh < 2; hh++) {
        float4 v0 = *(const float4*)(x + ((size_t)(b*C_ + r     )*H_ + h0 + hh)*W_ + w0 + q*4);
        float4 v1 = *(const float4*)(x + ((size_t)(b*C_ + 32 + r)*H_ + h0 + hh)*W_ + w0 + q*4);
        t[hh][0][r][q*4] = v0.x; t[hh][0][r][q*4+1] = v0.y; t[hh][0][r][q*4+2] = v0.z; t[hh][0][r][q*4+3] = v0.w;
        t[hh][1][r][q*4] = v1.x; t[hh][1][r][q*4+1] = v1.y; t[hh][1][r][q*4+2] = v1.z; t[hh][1][r][q*4+3] = v1.w;
    }
    __syncthreads();
#pragma unroll
    for (int hh = 0; hh < 2; hh++) {
        float4 o0, o1;
        o0.x = t[hh][0][q*4][r]; o0.y = t[hh][0][q*4+1][r]; o0.z = t[hh][0][q*4+2][r]; o0.w = t[hh][0][q*4+3][r];
        o1.x = t[hh][1][q*4][r]; o1.y = t[hh][1][q*4+1][r]; o1.z = t[hh][1][q*4+2][r]; o1.w = t[hh][1][q*4+3][r];
        float* dst = g_xn + ((size_t)(b*H_ + h0 + hh)*W_ + w0 + r)*C_;
        *(float4*)(dst + q*4)      = o0;
        *(float4*)(dst + 32 + q*4) = o1;
    }
}

// ---------------- weight repack into fp16 mma fragment order ----------------
__global__ void k_repack(const float* __restrict__ wgt, const float* __restrict__ omw) {
    int f = blockIdx.x*256 + threadIdx.x;
    if (f < K_*4*8*32) {                  // main weights
        int t  = f & 31;
        int j  = (f >> 5) & 7;
        int ks = (f >> 8) & 3;
        int k  = f >> 10;
        int o  = j*8 + (t >> 2);
        int c0 = ks*16 + 2*(t & 3);
        const float* wb = wgt + (size_t)o*C_*K_;
        uint32_t b0 = cvt_h2(wb[(c0+1)*K_ + k], wb[c0*K_ + k]);
        uint32_t b1 = cvt_h2(wb[(c0+9)*K_ + k], wb[(c0+8)*K_ + k]);
        g_wt3h[f] = make_uint2(b0, b1);
    } else if (f < K_*4*8*32 + K_*4*4*32) {
        int f2 = f - K_*4*8*32;
        int t  = f2 & 31;
        int j  = (f2 >> 5) & 3;
        int ks = (f2 >> 7) & 3;
        int k  = f2 >> 9;
        int oc = j*8 + (t >> 2);
        int c0 = ks*16 + 2*(t & 3);
        uint32_t b0 = 0, b1 = 0;
        if (oc < 27) {
            const float* wb = omw + (size_t)oc*C_*K_;
            b0 = cvt_h2(wb[(c0+1)*K_ + k], wb[c0*K_ + k]);
            b1 = cvt_h2(wb[(c0+9)*K_ + k], wb[(c0+8)*K_ + k]);
        }
        g_w1h[f2] = make_uint2(b0, b1);
    }
}

// ---------------- fused DCN: one block per (b, h) output row ----------------
// smem byte layout (46.4 KB -> 3 CTAs/SM)
#define SM_XS  0        // 18720 B : A tile half[130 px][72 c] ; om_s float[128 px][36] unions here
#define SM_SW  18720    // 18432 B : float4[9][128] corner weights
#define SM_I0  37152    // 4608  B : int[9][128]
#define SM_DD  41760    // 4608  B : int[9][128]
#define SM_TOT 46368

__global__ __launch_bounds__(256, 3)
void k_dcn(const float* __restrict__ bias, const float* __restrict__ om_bias,
           float* __restrict__ out) {
    extern __shared__ char sm[];
    uint32_t* xsu   = (uint32_t*)(sm + SM_XS);   // u32 view, row stride 36
    uint2*    xsu2  = (uint2*)(sm + SM_XS);      // uint2 view, row stride 18
    float*    om_s  = (float*)(sm + SM_XS);      // stride 36 floats: nests in own warp's xs rows
    float4*   s_w   = (float4*)(sm + SM_SW);
    int*      s_i0  = (int*)(sm + SM_I0);
    int*      s_d   = (int*)(sm + SM_DD);

    const int tid  = threadIdx.x;
    const int lane = tid & 31;
    const int w    = tid >> 5;
    const int tg   = lane >> 2;
    const int tig  = lane & 3;
    const int h    = blockIdx.x;
    const int b    = blockIdx.y;
    const int row0 = w*16 + tg;
    const float* xb = g_xn + (size_t)b*HW_*C_;

    // ---------- Phase 1: offset/mask conv (128px x 32oc x 576), 3 row-stagings ----------
    float4 acc1[4];
#pragma unroll
    for (int j = 0; j < 4; j++) acc1[j] = make_float4(0.f, 0.f, 0.f, 0.f);

    for (int ky = 0; ky < 3; ky++) {
        int yy = h + ky - 1;
        for (int e = tid; e < 2080; e += 256) {
            int c4 = e & 15, r = e >> 4;
            int xx = r - 1;
            float4 v = make_float4(0.f, 0.f, 0.f, 0.f);
            if (yy >= 0 && yy < H_ && xx >= 0 && xx < W_)
                v = *(const float4*)(xb + ((size_t)yy*W_ + xx)*C_ + c4*4);
            xsu2[r*18 + c4] = make_uint2(cvt_h2(v.y, v.x), cvt_h2(v.w, v.z));
        }
        __syncthreads();
#pragma unroll
        for (int ks = 0; ks < 4; ks++) {
#pragma unroll
            for (int kx = 0; kx < 3; kx++) {
                int ra = (row0 + kx)*36 + ks*8 + tig;
                uint32_t a0 = xsu[ra];
                uint32_t a1 = xsu[ra + 8*36];
                uint32_t a2 = xsu[ra + 4];
                uint32_t a3 = xsu[ra + 8*36 + 4];
                const uint2* gB = g_w1h + (size_t)(ky*3 + kx)*512;
#pragma unroll
                for (int j = 0; j < 4; j++) {
                    uint2 bf = __ldg(gB + (ks*4 + j)*32 + lane);
                    mma16(acc1[j], a0, a1, a2, a3, bf.x, bf.y);
                }
            }
        }
        __syncthreads();
    }

    // ---------- Phase 2a: write om fragments (stride 36 -> warp-band-local) ----------
#pragma unroll
    for (int j = 0; j < 4; j++) {
        int col = j*8 + tig*2;
        *(float2*)(om_s + row0*36 + col)     = make_float2(acc1[j].x, acc1[j].y);
        *(float2*)(om_s + (row0+8)*36 + col) = make_float2(acc1[j].z, acc1[j].w);
    }
    __syncwarp();

    // ---------- Phase 2b: per-warp bilinear prep for own px band ----------
    for (int e = lane; e < 144; e += 32) {
        int pxl = e & 15, k = e >> 4;
        int px  = w*16 + pxl;
        int ky = k / 3, kx = k - 3*ky;
        float oy = om_s[px*36 + k]      + __ldg(om_bias + k);
        float ox = om_s[px*36 + 9 + k]  + __ldg(om_bias + 9 + k);
        float mz = om_s[px*36 + 18 + k] + __ldg(om_bias + 18 + k);
        float mk = 1.f / (1.f + expf(-mz));
        float pyf = oy + (float)(h - 1 + ky);
        float pxf = ox + (float)(px - 1 + kx);
        float y0f = floorf(pyf), x0f = floorf(pxf);
        float ly = pyf - y0f, lx = pxf - x0f;
        int y0 = (int)y0f, x0 = (int)x0f;
        bool vy0 = (y0 >= 0)   & (y0 < H_);
        bool vy1 = (y0 >= -1)  & (y0 < H_-1);
        bool vx0 = (x0 >= 0)   & (x0 < W_);
        bool vx1 = (x0 >= -1)  & (x0 < W_-1);
        float w00 = (1.f-ly)*(1.f-lx)*mk * (float)(vy0 & vx0);
        float w01 = (1.f-ly)*lx*mk       * (float)(vy0 & vx1);
        float w10 = ly*(1.f-lx)*mk       * (float)(vy1 & vx0);
        float w11 = ly*lx*mk             * (float)(vy1 & vx1);
        int cy0 = min(max(y0, 0), H_-1),   cx0 = min(max(x0, 0), W_-1);
        int cy1 = min(max(y0+1, 0), H_-1), cx1 = min(max(x0+1, 0), W_-1);
        int se = k*128 + px;
        s_w[se]  = make_float4(w00, w01, w10, w11);
        s_i0[se] = cy0*W_ + cx0;
        s_d[se]  = (cx1 - cx0) | (((cy1 - cy0)*W_) << 16);
    }
    __syncwarp();

    // ---------- Phase 3: main DCN, fully warp-local (no block barriers) ----------
    float4 acc[8];
#pragma unroll
    for (int j = 0; j < 8; j++) acc[j] = make_float4(0.f, 0.f, 0.f, 0.f);

    for (int k = 0; k < K_; k++) {
        // stage own 16 px rows: 16 px x 16 c4 = 256 elems / 32 lanes
#pragma unroll
        for (int i = 0; i < 8; i++) {
            int e  = lane + i*32;
            int c4 = e & 15, pxl = e >> 4;
            int px = w*16 + pxl;
            int se = k*128 + px;
            float4 wv = s_w[se];
            int i0 = s_i0[se];
            int d  = s_d[se];
            int dx  = d & 0xffff;
            int dyw = d >> 16;
            const float* p00 = xb + (size_t)i0*C_ + c4*4;
            float4 A  = *(const float4*)(p00);
            float4 Bb = *(const float4*)(p00 + dx*C_);
            float4 Cc = *(const float4*)(p00 + dyw*C_);
            float4 Dd = *(const float4*)(p00 + (size_t)(dyw+dx)*C_);
            float r0 = wv.x*A.x + wv.y*Bb.x + wv.z*Cc.x + wv.w*Dd.x;
            float r1 = wv.x*A.y + wv.y*Bb.y + wv.z*Cc.y + wv.w*Dd.y;
            float r2 = wv.x*A.z + wv.y*Bb.z + wv.z*Cc.z + wv.w*Dd.z;
            float r3 = wv.x*A.w + wv.y*Bb.w + wv.z*Cc.w + wv.w*Dd.w;
            xsu2[px*18 + c4] = make_uint2(cvt_h2(r1, r0), cvt_h2(r3, r2));
        }
        __syncwarp();
        const uint2* gB = g_wt3h + (size_t)k*1024;
#pragma unroll
        for (int ks = 0; ks < 4; ks++) {
            int ra = row0*36 + ks*8 + tig;
            uint32_t a0 = xsu[ra];
            uint32_t a1 = xsu[ra + 8*36];
            uint32_t a2 = xsu[ra + 4];
            uint32_t a3 = xsu[ra + 8*36 + 4];
#pragma unroll
            for (int j = 0; j < 8; j++) {
                uint2 bf = __ldg(gB + (ks*8 + j)*32 + lane);
                mma16(acc[j], a0, a1, a2, a3, bf.x, bf.y);
            }
        }
        __syncwarp();
    }

    // ---------- Epilogue: NCHW store + bias ----------
#pragma unroll
    for (int j = 0; j < 8; j++) {
        int o = j*8 + tig*2;
        float b0v = __ldg(bias + o);
        float b1v = __ldg(bias + o + 1);
        size_t base0 = (((size_t)b*O_ + o    )*H_ + h)*W_;
        size_t base1 = (((size_t)b*O_ + o + 1)*H_ + h)*W_;
        out[base0 + row0]     = acc[j].x + b0v;
        out[base1 + row0]     = acc[j].y + b1v;
        out[base0 + row0 + 8] = acc[j].z + b0v;
        out[base1 + row0 + 8] = acc[j].w + b1v;
    }
}

extern "C" void kernel_launch(void* const* d_in, const int* in_sizes, int n_in,
                              void* d_out, int out_size) {
    const float* x         = (const float*)d_in[0];
    const float* weight    = (const float*)d_in[1];
    const float* bias      = (const float*)d_in[2];
    const float* om_weight = (const float*)d_in[3];
    const float* om_bias   = (const float*)d_in[4];
    float* out = (float*)d_out;

    int B = in_sizes[0] / (C_*H_*W_);
    if (B < 1) B = 1;
    if (B > Bmax) B = Bmax;

    cudaFuncSetAttribute(k_dcn, cudaFuncAttributeMaxDynamicSharedMemorySize, SM_TOT);

    k_transpose<<<dim3(W_/32, H_/2, B), 256>>>(x);
    int nrep = K_*4*8*32 + K_*4*4*32;
    k_repack<<<(nrep + 255)/256, 256>>>(weight, om_weight);
    k_dcn<<<dim3(H_, B), 256, SM_TOT>>>(bias, om_bias, out);
}

// round 10
// speedup vs baseline: 1.1423x; 1.1423x over previous
#include <cuda_runtime.h>
#include <math.h>
#include <stdint.h>

#define Bmax 4
#define C_ 64
#define H_ 128
#define W_ 128
#define O_ 64
#define K_ 9
#define HW_ (H_*W_)

__device__ __forceinline__ uint32_t cvt_h2(float hi, float lo) {
    uint32_t r; asm("cvt.rn.f16x2.f32 %0, %1, %2;" : "=r"(r) : "f"(hi), "f"(lo)); return r;
}
__device__ __forceinline__ void mma16(float4 &d, uint32_t a0, uint32_t a1, uint32_t a2, uint32_t a3,
                                      uint32_t b0, uint32_t b1) {
    asm("mma.sync.aligned.m16n8k16.row.col.f32.f16.f16.f32 "
        "{%0,%1,%2,%3},{%4,%5,%6,%7},{%8,%9},{%0,%1,%2,%3};"
        : "+f"(d.x), "+f"(d.y), "+f"(d.z), "+f"(d.w)
        : "r"(a0), "r"(a1), "r"(a2), "r"(a3), "r"(b0), "r"(b1));
}

// ---------------- device scratch ----------------
__device__ float g_xn[Bmax*HW_*C_ + 16384];   // NHWC x (fp32), padded
// fp16 B fragments, per-thread order (uint2 = {b0,b1} half2 pairs):
__device__ uint2 g_wt3h[K_*4*8*32];           // main: [k][ks(4)][j(8)][t(32)]
__device__ uint2 g_w1h[K_*4*4*32];            // om:   [k][ks(4)][j(4)][t(32)]

// ---------------- NCHW -> NHWC transpose (2 h-rows per block) ----------------
__global__ __launch_bounds__(256)
void k_transpose(const float* __restrict__ x) {
    __shared__ float t[2][2][32][33];
    int b  = blockIdx.z;
    int h0 = blockIdx.y * 2;
    int w0 = blockIdx.x * 32;
    int tid = threadIdx.x;
    int r  = tid >> 3;
    int q  = tid & 7;
#pragma unroll
    for (int hh = 0; hh < 2; hh++) {
        float4 v0 = *(const float4*)(x + ((size_t)(b*C_ + r     )*H_ + h0 + hh)*W_ + w0 + q*4);
        float4 v1 = *(const float4*)(x + ((size_t)(b*C_ + 32 + r)*H_ + h0 + hh)*W_ + w0 + q*4);
        t[hh][0][r][q*4] = v0.x; t[hh][0][r][q*4+1] = v0.y; t[hh][0][r][q*4+2] = v0.z; t[hh][0][r][q*4+3] = v0.w;
        t[hh][1][r][q*4] = v1.x; t[hh][1][r][q*4+1] = v1.y; t[hh][1][r][q*4+2] = v1.z; t[hh][1][r][q*4+3] = v1.w;
    }
    __syncthreads();
#pragma unroll
    for (int hh = 0; hh < 2; hh++) {
        float4 o0, o1;
        o0.x = t[hh][0][q*4][r]; o0.y = t[hh][0][q*4+1][r]; o0.z = t[hh][0][q*4+2][r]; o0.w = t[hh][0][q*4+3][r];
        o1.x = t[hh][1][q*4][r]; o1.y = t[hh][1][q*4+1][r]; o1.z = t[hh][1][q*4+2][r]; o1.w = t[hh][1][q*4+3][r];
        float* dst = g_xn + ((size_t)(b*H_ + h0 + hh)*W_ + w0 + r)*C_;
        *(float4*)(dst + q*4)      = o0;
        *(float4*)(dst + 32 + q*4) = o1;
    }
}

// ---------------- weight repack into fp16 mma fragment order ----------------
__global__ void k_repack(const float* __restrict__ wgt, const float* __restrict__ omw) {
    int f = blockIdx.x*256 + threadIdx.x;
    if (f < K_*4*8*32) {                  // main weights
        int t  = f & 31;
        int j  = (f >> 5) & 7;
        int ks = (f >> 8) & 3;
        int k  = f >> 10;
        int o  = j*8 + (t >> 2);
        int c0 = ks*16 + 2*(t & 3);
        const float* wb = wgt + (size_t)o*C_*K_;
        uint32_t b0 = cvt_h2(wb[(c0+1)*K_ + k], wb[c0*K_ + k]);
        uint32_t b1 = cvt_h2(wb[(c0+9)*K_ + k], wb[(c0+8)*K_ + k]);
        g_wt3h[f] = make_uint2(b0, b1);
    } else if (f < K_*4*8*32 + K_*4*4*32) {
        int f2 = f - K_*4*8*32;
        int t  = f2 & 31;
        int j  = (f2 >> 5) & 3;
        int ks = (f2 >> 7) & 3;
        int k  = f2 >> 9;
        int oc = j*8 + (t >> 2);
        int c0 = ks*16 + 2*(t & 3);
        uint32_t b0 = 0, b1 = 0;
        if (oc < 27) {
            const float* wb = omw + (size_t)oc*C_*K_;
            b0 = cvt_h2(wb[(c0+1)*K_ + k], wb[c0*K_ + k]);
            b1 = cvt_h2(wb[(c0+9)*K_ + k], wb[(c0+8)*K_ + k]);
        }
        g_w1h[f2] = make_uint2(b0, b1);
    }
}

// ---------------- fused DCN: one block per (b, h) output row ----------------
// smem byte layout (89.7 KB -> 2 CTAs/SM), double-buffered A and B tiles
#define SM_A0  0        // 18720 B : A tile buf0, half[130 px][72 c] (row pitch 144B)
#define SM_A1  18720    // 18720 B : A tile buf1
#define SM_B0  37440    // 12288 B : B frag buf0 (ph1: 3 taps x 4KB; ph3: 8KB)
#define SM_B1  49728    // 12288 B : B frag buf1
#define SM_SW  62016    // 18432 B : float4[9][128] corner weights
#define SM_I0  80448    // 4608  B : int[9][128]
#define SM_DD  85056    // 4608  B : int[9][128]
#define SM_TOT 89664

__global__ __launch_bounds__(256, 2)
void k_dcn(const float* __restrict__ bias, const float* __restrict__ om_bias,
           float* __restrict__ out) {
    extern __shared__ char sm[];
    float*    om_s  = (float*)(sm + SM_A0);      // stride-36 floats; A dead when used
    float4*   s_w   = (float4*)(sm + SM_SW);
    int*      s_i0  = (int*)(sm + SM_I0);
    int*      s_d   = (int*)(sm + SM_DD);

    const int tid  = threadIdx.x;
    const int lane = tid & 31;
    const int w    = tid >> 5;
    const int tg   = lane >> 2;
    const int tig  = lane & 3;
    const int h    = blockIdx.x;
    const int b    = blockIdx.y;
    const int row0 = w*16 + tg;
    const float* xb = g_xn + (size_t)b*HW_*C_;

    // buffer accessors
    auto bufA_u2 = [&](int i) { return (uint2*)(sm + (i ? SM_A1 : SM_A0)); };     // row stride 18
    auto bufA_u  = [&](int i) { return (uint32_t*)(sm + (i ? SM_A1 : SM_A0)); };  // row stride 36
    auto bufB_u2 = [&](int i) { return (uint2*)(sm + (i ? SM_B1 : SM_B0)); };
    auto bufB_u4 = [&](int i) { return (uint4*)(sm + (i ? SM_B1 : SM_B0)); };

    // ---------- Phase 1: offset/mask conv (128px x 32oc x 576), pipelined over ky ----------
    float4 acc1[4];
#pragma unroll
    for (int j = 0; j < 4; j++) acc1[j] = make_float4(0.f, 0.f, 0.f, 0.f);

    // stage helpers (phase 1)
    auto stageA1 = [&](int ky, int buf) {
        int yy = h + ky - 1;
        uint2* xs2 = bufA_u2(buf);
        for (int e = tid; e < 2080; e += 256) {
            int c4 = e & 15, r = e >> 4;
            int xx = r - 1;
            float4 v = make_float4(0.f, 0.f, 0.f, 0.f);
            if (yy >= 0 && yy < H_ && xx >= 0 && xx < W_)
                v = *(const float4*)(xb + ((size_t)yy*W_ + xx)*C_ + c4*4);
            xs2[r*18 + c4] = make_uint2(cvt_h2(v.y, v.x), cvt_h2(v.w, v.z));
        }
    };
    auto stageB1 = [&](int ky, int buf) {
        const uint4* src = (const uint4*)(g_w1h + (size_t)ky*3*512);
        uint4* dst = bufB_u4(buf);
        for (int e = tid; e < 768; e += 256) dst[e] = src[e];
    };

    stageA1(0, 0); stageB1(0, 0);
    __syncthreads();
    for (int ky = 0; ky < 3; ky++) {
        int cur = ky & 1;
        if (ky < 2) { stageA1(ky + 1, cur ^ 1); stageB1(ky + 1, cur ^ 1); }
        const uint32_t* xsu = bufA_u(cur);
        const uint2*    bB  = bufB_u2(cur);
#pragma unroll
        for (int ks = 0; ks < 4; ks++) {
#pragma unroll
            for (int kx = 0; kx < 3; kx++) {
                int ra = (row0 + kx)*36 + ks*8 + tig;
                uint32_t a0 = xsu[ra];
                uint32_t a1 = xsu[ra + 8*36];
                uint32_t a2 = xsu[ra + 4];
                uint32_t a3 = xsu[ra + 8*36 + 4];
#pragma unroll
                for (int j = 0; j < 4; j++) {
                    uint2 bf = bB[kx*512 + (ks*4 + j)*32 + lane];
                    mma16(acc1[j], a0, a1, a2, a3, bf.x, bf.y);
                }
            }
        }
        __syncthreads();
    }

    // ---------- Phase 2a: write om fragments to smem [px][36] (A0 region, dead) ----------
#pragma unroll
    for (int j = 0; j < 4; j++) {
        int col = j*8 + tig*2;
        *(float2*)(om_s + row0*36 + col)     = make_float2(acc1[j].x, acc1[j].y);
        *(float2*)(om_s + (row0+8)*36 + col) = make_float2(acc1[j].z, acc1[j].w);
    }
    __syncthreads();

    // ---------- Phase 2b: bilinear sampling prep per (px, k) ----------
    for (int e = tid; e < 1152; e += 256) {
        int px = e & 127, k = e >> 7;
        int ky = k / 3, kx = k - 3*ky;
        float oy = om_s[px*36 + k]      + __ldg(om_bias + k);
        float ox = om_s[px*36 + 9 + k]  + __ldg(om_bias + 9 + k);
        float mz = om_s[px*36 + 18 + k] + __ldg(om_bias + 18 + k);
        float mk = 1.f / (1.f + expf(-mz));
        float pyf = oy + (float)(h - 1 + ky);
        float pxf = ox + (float)(px - 1 + kx);
        float y0f = floorf(pyf), x0f = floorf(pxf);
        float ly = pyf - y0f, lx = pxf - x0f;
        int y0 = (int)y0f, x0 = (int)x0f;
        bool vy0 = (y0 >= 0)   & (y0 < H_);
        bool vy1 = (y0 >= -1)  & (y0 < H_-1);
        bool vx0 = (x0 >= 0)   & (x0 < W_);
        bool vx1 = (x0 >= -1)  & (x0 < W_-1);
        float w00 = (1.f-ly)*(1.f-lx)*mk * (float)(vy0 & vx0);
        float w01 = (1.f-ly)*lx*mk       * (float)(vy0 & vx1);
        float w10 = ly*(1.f-lx)*mk       * (float)(vy1 & vx0);
        float w11 = ly*lx*mk             * (float)(vy1 & vx1);
        int cy0 = min(max(y0, 0), H_-1),   cx0 = min(max(x0, 0), W_-1);
        int cy1 = min(max(y0+1, 0), H_-1), cx1 = min(max(x0+1, 0), W_-1);
        s_w[e]  = make_float4(w00, w01, w10, w11);
        s_i0[e] = cy0*W_ + cx0;
        s_d[e]  = (cx1 - cx0) | (((cy1 - cy0)*W_) << 16);
    }
    __syncthreads();

    // ---------- Phase 3: main DCN (128px x 64o x 576), pipelined over taps ----------
    float4 acc[8];
#pragma unroll
    for (int j = 0; j < 8; j++) acc[j] = make_float4(0.f, 0.f, 0.f, 0.f);

    auto stageA3 = [&](int k, int buf) {
        uint2* xs2 = bufA_u2(buf);
        for (int e = tid; e < 2048; e += 256) {
            int c4 = e & 15, px = e >> 4;
            int se = k*128 + px;
            float4 wv = s_w[se];
            int i0 = s_i0[se];
            int d  = s_d[se];
            int dx  = d & 0xffff;
            int dyw = d >> 16;
            const float* p00 = xb + (size_t)i0*C_ + c4*4;
            float4 A  = *(const float4*)(p00);
            float4 Bb = *(const float4*)(p00 + dx*C_);
            float4 Cc = *(const float4*)(p00 + dyw*C_);
            float4 Dd = *(const float4*)(p00 + (size_t)(dyw+dx)*C_);
            float r0 = wv.x*A.x + wv.y*Bb.x + wv.z*Cc.x + wv.w*Dd.x;
            float r1 = wv.x*A.y + wv.y*Bb.y + wv.z*Cc.y + wv.w*Dd.y;
            float r2 = wv.x*A.z + wv.y*Bb.z + wv.z*Cc.z + wv.w*Dd.z;
            float r3 = wv.x*A.w + wv.y*Bb.w + wv.z*Cc.w + wv.w*Dd.w;
            xs2[px*18 + c4] = make_uint2(cvt_h2(r1, r0), cvt_h2(r3, r2));
        }
    };
    auto stageB3 = [&](int k, int buf) {
        const uint4* src = (const uint4*)(g_wt3h + (size_t)k*1024);
        uint4* dst = bufB_u4(buf);
        for (int e = tid; e < 512; e += 256) dst[e] = src[e];
    };

    stageA3(0, 0); stageB3(0, 0);
    __syncthreads();
    for (int k = 0; k < K_; k++) {
        int cur = k & 1;
        if (k < K_ - 1) { stageA3(k + 1, cur ^ 1); stageB3(k + 1, cur ^ 1); }
        const uint32_t* xsu = bufA_u(cur);
        const uint2*    bB  = bufB_u2(cur);
#pragma unroll
        for (int ks = 0; ks < 4; ks++) {
            int ra = row0*36 + ks*8 + tig;
            uint32_t a0 = xsu[ra];
            uint32_t a1 = xsu[ra + 8*36];
            uint32_t a2 = xsu[ra + 4];
            uint32_t a3 = xsu[ra + 8*36 + 4];
#pragma unroll
            for (int j = 0; j < 8; j++) {
                uint2 bf = bB[(ks*8 + j)*32 + lane];
                mma16(acc[j], a0, a1, a2, a3, bf.x, bf.y);
            }
        }
        __syncthreads();
    }

    // ---------- Epilogue: NCHW store + bias ----------
#pragma unroll
    for (int j = 0; j < 8; j++) {
        int o = j*8 + tig*2;
        float b0v = __ldg(bias + o);
        float b1v = __ldg(bias + o + 1);
        size_t base0 = (((size_t)b*O_ + o    )*H_ + h)*W_;
        size_t base1 = (((size_t)b*O_ + o + 1)*H_ + h)*W_;
        out[base0 + row0]     = acc[j].x + b0v;
        out[base1 + row0]     = acc[j].y + b1v;
        out[base0 + row0 + 8] = acc[j].z + b0v;
        out[base1 + row0 + 8] = acc[j].w + b1v;
    }
}

extern "C" void kernel_launch(void* const* d_in, const int* in_sizes, int n_in,
                              void* d_out, int out_size) {
    const float* x         = (const float*)d_in[0];
    const float* weight    = (const float*)d_in[1];
    const float* bias      = (const float*)d_in[2];
    const float* om_weight = (const float*)d_in[3];
    const float* om_bias   = (const float*)d_in[4];
    float* out = (float*)d_out;

    int B = in_sizes[0] / (C_*H_*W_);
    if (B < 1) B = 1;
    if (B > Bmax) B = Bmax;

    cudaFuncSetAttribute(k_dcn, cudaFuncAttributeMaxDynamicSharedMemorySize, SM_TOT);

    k_transpose<<<dim3(W_/32, H_/2, B), 256>>>(x);
    int nrep = K_*4*8*32 + K_*4*4*32;
    k_repack<<<(nrep + 255)/256, 256>>>(weight, om_weight);
    k_dcn<<<dim3(H_, B), 256, SM_TOT>>>(bias, om_bias, out);
}